// round 7
// baseline (speedup 1.0000x reference)
#include <cuda_runtime.h>
#include <cstdint>
#include <cstddef>

#define Bsz 8
#define Cc  32
#define Oo  64
#define Hh  64
#define Ww  64
#define Kk  9

constexpr int OTILE = 4;                  // o's per block (all owned by every thread)
constexpr int SEG   = Ww * Kk;            // 576 floats per (o,c,h)
constexpr int WTILE = OTILE * SEG;        // 2304 floats per c
constexpr int XROWS = 3;
constexpr int XCOLP = 72;                 // [3]=col -1, [4..67]=cols 0..63, [68]=col 64
constexpr int XTILE = Bsz * XROWS * XCOLP;// 1728 floats per c
constexpr int SMEM_BYTES = (2 * WTILE + 2 * XTILE) * 4;  // 32256 B
constexpr int WC_STRIDE = Hh * SEG;
constexpr int XC_STRIDE = Hh * Ww;

typedef unsigned long long ull;

__device__ __forceinline__ void cp16(float* dst_smem, const float* src, int sz) {
    uint32_t a = (uint32_t)__cvta_generic_to_shared(dst_smem);
    asm volatile("cp.async.cg.shared.global [%0], [%1], 16, %2;"
                 :: "r"(a), "l"(src), "r"(sz));
}
__device__ __forceinline__ ull pack2(float lo, float hi) {
    ull r;
    asm("mov.b64 %0, {%1, %2};" : "=l"(r) : "f"(lo), "f"(hi));
    return r;
}
__device__ __forceinline__ void unpack2(float& lo, float& hi, ull v) {
    asm("mov.b64 {%0, %1}, %2;" : "=f"(lo), "=f"(hi) : "l"(v));
}
__device__ __forceinline__ void fma2(ull& d, ull a, ull b) {
    asm("fma.rn.f32x2 %0, %1, %2, %0;" : "+l"(d) : "l"(a), "l"(b));
}

__global__ void __launch_bounds__(64, 6)
lc2d_kernel(const float* __restrict__ x,
            const float* __restrict__ wt,
            float* __restrict__ out)
{
    extern __shared__ float smem[];
    float* wsm = smem;                    // [2][WTILE]
    float* xsm = smem + 2 * WTILE;        // [2][XTILE]

    const int tx = threadIdx.x;           // 64 threads: one w column each
    const int w  = tx;
    const int h  = blockIdx.x;
    const int ob = blockIdx.y * OTILE;

    // one-time halo zeros: cols 3 and 68 of every (buf,b,row) = 96 slots
    #pragma unroll
    for (int i = 0; i < 2; i++) {
        int t = tx + i * 64;
        if (t < 96) {
            int bufsel = t / 48;
            int q      = t - bufsel * 48;
            int b      = q / 6;
            int rr     = q - b * 6;
            int r      = rr >> 1;
            int side   = rr & 1;
            xsm[bufsel * XTILE + (b * XROWS + r) * XCOLP + (side ? 68 : 3)] = 0.f;
        }
    }

    // ---- loop-invariant staging descriptors (marching gmem offsets) ----
    // weights: 576 float4 / 64 threads = 9 each
    int wgo[9], wso[9];
    #pragma unroll
    for (int i = 0; i < 9; i++) {
        int idx = tx + i * 64;
        int seg = idx / 144;              // 0..3
        int pos = idx - seg * 144;
        wgo[i] = (((ob + seg) * Cc) * Hh + h) * SEG + pos * 4;
        wso[i] = seg * SEG + pos * 4;
    }
    // x: 384 float4 / 64 threads = 6 each
    int xgo[6], xso[6], xsz[6];
    #pragma unroll
    for (int i = 0; i < 6; i++) {
        int idx = tx + i * 64;
        int b   = idx / 48;
        int rem = idx - b * 48;
        int r   = rem >> 4;
        int j   = rem & 15;
        int grow = h - 1 + r;
        xsz[i]  = (grow >= 0 && grow < Hh) ? 16 : 0;
        int gr  = grow < 0 ? 0 : (grow > Hh - 1 ? Hh - 1 : grow);
        xgo[i]  = ((b * Cc) * Hh + gr) * Ww + j * 4;
        xso[i]  = (b * XROWS + r) * XCOLP + 4 + j * 4;
    }

    // accumulators: [o][batch-pair] packed (halves = batches 2bp, 2bp+1)
    ull acc2[OTILE][4];
    #pragma unroll
    for (int oo = 0; oo < OTILE; oo++)
        #pragma unroll
        for (int bp = 0; bp < 4; bp++)
            acc2[oo][bp] = 0ull;

    auto stage = [&](int buf) {
        float* wb = wsm + buf * WTILE;
        #pragma unroll
        for (int i = 0; i < 9; i++) {
            cp16(wb + wso[i], wt + wgo[i], 16);
            wgo[i] += WC_STRIDE;
        }
        float* xb = xsm + buf * XTILE;
        #pragma unroll
        for (int i = 0; i < 6; i++) {
            cp16(xb + xso[i], x + xgo[i], xsz[i]);
            xgo[i] += XC_STRIDE;
        }
    };

    // depth-2 prologue
    stage(0);
    asm volatile("cp.async.commit_group;");
    stage(1);
    asm volatile("cp.async.commit_group;");

    for (int c = 0; c < Cc; c++) {
        const int cur = c & 1;
        asm volatile("cp.async.wait_group 1;");
        __syncthreads();                       // stage(c) visible (2-warp barrier: cheap)

        const float* wb = wsm + cur * WTILE + w * Kk;
        const float* xb = xsm + cur * XTILE + 3 + w;

        // k-row chunking keeps live packed weights at 12 ull
        #pragma unroll
        for (int r = 0; r < 3; r++) {
            ull wr2[OTILE][3];
            #pragma unroll
            for (int oo = 0; oo < OTILE; oo++)
                #pragma unroll
                for (int kk = 0; kk < 3; kk++) {
                    float f = wb[oo * SEG + r * 3 + kk];
                    wr2[oo][kk] = pack2(f, f);
                }
            #pragma unroll
            for (int bp = 0; bp < 4; bp++) {
                const float* xlo = xb + (2 * bp)     * (XROWS * XCOLP) + r * XCOLP;
                const float* xhi = xb + (2 * bp + 1) * (XROWS * XCOLP) + r * XCOLP;
                ull xv2[3];
                #pragma unroll
                for (int kk = 0; kk < 3; kk++)
                    xv2[kk] = pack2(xlo[kk], xhi[kk]);
                #pragma unroll
                for (int oo = 0; oo < OTILE; oo++)
                    #pragma unroll
                    for (int kk = 0; kk < 3; kk++)
                        fma2(acc2[oo][bp], wr2[oo][kk], xv2[kk]);
            }
        }

        __syncthreads();                       // all reads of buf `cur` done
        if (c + 2 < Cc)
            stage(cur);                        // refill just-consumed buffer
        asm volatile("cp.async.commit_group;");
    }

    // epilogue: coalesced stores (lanes = consecutive w)
    float* op = out + ((size_t)ob * Hh + h) * Ww + w;
    #pragma unroll
    for (int bp = 0; bp < 4; bp++)
        #pragma unroll
        for (int oo = 0; oo < OTILE; oo++) {
            float lo, hi;
            unpack2(lo, hi, acc2[oo][bp]);
            op[(size_t)((2 * bp)     * Oo + oo) * (Hh * Ww)] = lo;
            op[(size_t)((2 * bp + 1) * Oo + oo) * (Hh * Ww)] = hi;
        }
}

extern "C" void kernel_launch(void* const* d_in, const int* in_sizes, int n_in,
                              void* d_out, int out_size)
{
    const float* x  = (const float*)d_in[0];
    const float* wt = (const float*)d_in[1];
    float* out      = (float*)d_out;

    cudaFuncSetAttribute(lc2d_kernel,
                         cudaFuncAttributeMaxDynamicSharedMemorySize, SMEM_BYTES);

    dim3 grid(Hh, Oo / OTILE);   // 64 x 16 = 1024 blocks of 64 threads
    lc2d_kernel<<<grid, 64, SMEM_BYTES>>>(x, wt, out);
}

// round 9
// speedup vs baseline: 1.0762x; 1.0762x over previous
#include <cuda_runtime.h>
#include <cstdint>
#include <cstddef>

#define Bsz 8
#define Cc  32
#define Oo  64
#define Hh  64
#define Ww  64
#define Kk  9

constexpr int OTILE = 8;                  // o's per block
constexpr int SEG   = Ww * Kk;            // 576 floats per (o,c,h)
constexpr int WTILE = OTILE * SEG;        // 4608 floats per c (18432 B)
constexpr int XROWS = 3;
constexpr int XCOLP = 72;                 // [3]=col -1, [4..67]=cols 0..63, [68]=col 64
constexpr int XTILE = Bsz * XROWS * XCOLP;// 1728 floats per c
constexpr int SMEM_BYTES = 16 + (2 * WTILE + 2 * XTILE) * 4;   // 50704 B -> 4 CTAs/SM
constexpr int WC_STRIDE = Hh * SEG;
constexpr int XC_STRIDE = Hh * Ww;
constexpr uint32_t WSEG_BYTES = SEG * 4;  // 2304
constexpr uint32_t XROW_BYTES = Ww * 4;   // 256

typedef unsigned long long ull;

__device__ __forceinline__ ull pack2(float lo, float hi) {
    ull r; asm("mov.b64 %0, {%1, %2};" : "=l"(r) : "f"(lo), "f"(hi)); return r;
}
__device__ __forceinline__ void unpack2(float& lo, float& hi, ull v) {
    asm("mov.b64 {%0, %1}, %2;" : "=f"(lo), "=f"(hi) : "l"(v));
}
__device__ __forceinline__ void fma2(ull& d, ull a, ull b) {
    asm("fma.rn.f32x2 %0, %1, %2, %0;" : "+l"(d) : "l"(a), "l"(b));
}

__device__ __forceinline__ void mbar_init(uint32_t mbar, uint32_t cnt) {
    asm volatile("mbarrier.init.shared.b64 [%0], %1;" :: "r"(mbar), "r"(cnt) : "memory");
}
__device__ __forceinline__ void mbar_expect_tx(uint32_t mbar, uint32_t bytes) {
    asm volatile("mbarrier.arrive.expect_tx.shared.b64 _, [%0], %1;"
                 :: "r"(mbar), "r"(bytes) : "memory");
}
__device__ __forceinline__ void mbar_wait(uint32_t mbar, uint32_t parity) {
    asm volatile(
        "{\n\t.reg .pred P;\n\t"
        "W%=:\n\t"
        "mbarrier.try_wait.parity.acquire.cta.shared::cta.b64 P, [%0], %1, 0x989680;\n\t"
        "@!P bra W%=;\n\t}"
        :: "r"(mbar), "r"(parity) : "memory");
}
// 1D bulk copy global->shared with transaction-byte completion
__device__ __forceinline__ void bulk_cp(uint32_t dst, const float* src,
                                        uint32_t bytes, uint32_t mbar) {
    asm volatile("cp.async.bulk.shared::cta.global.mbarrier::complete_tx::bytes "
                 "[%0], [%1], %2, [%3];"
                 :: "r"(dst), "l"(src), "r"(bytes), "r"(mbar) : "memory");
}

__global__ void __launch_bounds__(128, 4)
lc2d_kernel(const float* __restrict__ x,
            const float* __restrict__ wt,
            float* __restrict__ out)
{
    extern __shared__ float smem[];
    const uint32_t sbase = (uint32_t)__cvta_generic_to_shared(smem);
    float* wsm = smem + 4;                 // [2][WTILE]
    float* xsm = smem + 4 + 2 * WTILE;     // [2][XTILE]
    const uint32_t wsm_u = sbase + 16;
    const uint32_t xsm_u = sbase + 16 + 2 * WTILE * 4;
    const uint32_t mbar0 = sbase;
    const uint32_t mbar1 = sbase + 8;

    const int tid = threadIdx.x;           // 128 threads
    const int w   = tid & 63;
    const int oq  = tid >> 6;              // 0..1
    const int h   = blockIdx.x;
    const int ob  = blockIdx.y * OTILE;
    const int o0  = ob + oq * 4;

    // ---- one-time zero init: halo cols + OOB rows (bulk copies never touch these) ----
    if (tid < 96) {
        int bufsel = tid / 48;
        int q      = tid - bufsel * 48;
        int b      = q / 6;
        int rr     = q - b * 6;
        int r      = rr >> 1;
        int side   = rr & 1;
        xsm[bufsel * XTILE + (b * XROWS + r) * XCOLP + (side ? 68 : 3)] = 0.f;
    }
    if (h == 0 || h == Hh - 1) {
        int badrow = (h == 0) ? 0 : 2;
        #pragma unroll
        for (int i = 0; i < 8; i++) {
            int idx = tid + i * 128;       // 1024 floats: 2 bufs x 8 b x 64 cols
            int bufsel = idx >> 9;
            int rem    = idx & 511;
            int b      = rem >> 6;
            int col    = rem & 63;
            xsm[bufsel * XTILE + (b * XROWS + badrow) * XCOLP + 4 + col] = 0.f;
        }
    }

    // ---- staging roles ----
    // threads 64..71: weight segment seg = tid-64  (OTILE=8 segments, 2304 B each)
    // threads  0..23: x row (b = tid/3, r = tid%3) (256 B each, if in-bounds)
    const int  wseg   = tid - 64;
    const bool is_wst = (tid >= 64 && tid < 64 + OTILE);
    int  wsrc0 = 0; uint32_t wdst_off = 0;
    if (is_wst) {
        wsrc0    = (((ob + wseg) * Cc) * Hh + h) * SEG;
        wdst_off = (uint32_t)(wseg * SEG) * 4;
    }
    const bool is_xst = (tid < 24);
    bool xvalid = false; int xsrc0 = 0; uint32_t xdst_off = 0;
    if (is_xst) {
        int xb_ = tid / 3, xr_ = tid - (tid / 3) * 3;
        int grow = h - 1 + xr_;
        xvalid = (grow >= 0 && grow < Hh);
        xsrc0  = ((xb_ * Cc) * Hh + grow) * Ww;
        xdst_off = (uint32_t)((xb_ * XROWS + xr_) * XCOLP + 4) * 4;
    }
    const int nrows = XROWS - (h == 0) - (h == Hh - 1);
    const uint32_t TXBYTES = OTILE * WSEG_BYTES + (uint32_t)(nrows * Bsz) * XROW_BYTES;

    auto issue_bulks = [&](int c) {        // data movement for channel c into buffer c&1
        const int buf = c & 1;
        const uint32_t mb = (buf ? mbar1 : mbar0);
        if (is_wst)
            bulk_cp(wsm_u + (uint32_t)buf * (WTILE * 4) + wdst_off,
                    wt + wsrc0 + c * WC_STRIDE, WSEG_BYTES, mb);
        if (is_xst && xvalid)
            bulk_cp(xsm_u + (uint32_t)buf * (XTILE * 4) + xdst_off,
                    x + xsrc0 + c * XC_STRIDE, XROW_BYTES, mb);
    };

    // prologue: arm both barriers FIRST (expect_tx strictly before any bulk issues)
    if (tid == 0) {
        mbar_init(mbar0, 1);
        mbar_init(mbar1, 1);
        mbar_expect_tx(mbar0, TXBYTES);
        mbar_expect_tx(mbar1, TXBYTES);
    }
    __syncthreads();                       // zeros + init + arming visible
    issue_bulks(0);
    issue_bulks(1);

    ull acc2[4][4];
    #pragma unroll
    for (int oo = 0; oo < 4; oo++)
        #pragma unroll
        for (int bp = 0; bp < 4; bp++)
            acc2[oo][bp] = 0ull;

    for (int c = 0; c < Cc; c++) {
        const int cur = c & 1;
        mbar_wait(cur ? mbar1 : mbar0, (c >> 1) & 1);   // stage(c) complete (acquire)

        const float* wb = wsm + cur * WTILE + oq * 4 * SEG + w * Kk;
        const float* xb = xsm + cur * XTILE + 3 + w;

        #pragma unroll
        for (int r = 0; r < 3; r++) {
            ull wr2[4][3];
            #pragma unroll
            for (int oo = 0; oo < 4; oo++)
                #pragma unroll
                for (int kk = 0; kk < 3; kk++) {
                    float f = wb[oo * SEG + r * 3 + kk];
                    wr2[oo][kk] = pack2(f, f);
                }
            #pragma unroll
            for (int bp = 0; bp < 4; bp++) {
                const float* xlo = xb + (2 * bp)     * (XROWS * XCOLP) + r * XCOLP;
                const float* xhi = xb + (2 * bp + 1) * (XROWS * XCOLP) + r * XCOLP;
                ull xv2[3];
                #pragma unroll
                for (int kk = 0; kk < 3; kk++)
                    xv2[kk] = pack2(xlo[kk], xhi[kk]);
                #pragma unroll
                for (int oo = 0; oo < 4; oo++)
                    #pragma unroll
                    for (int kk = 0; kk < 3; kk++)
                        fma2(acc2[oo][bp], wr2[oo][kk], xv2[kk]);
            }
        }

        if (c + 2 < Cc) {
            // re-arm the barrier we just consumed BEFORE the barrier that
            // releases the stagers -> expect_tx ordered before all bulk issues
            if (tid == 0)
                mbar_expect_tx(cur ? mbar1 : mbar0, TXBYTES);
            __syncthreads();               // all warps done READING buffer `cur`
            issue_bulks(c + 2);            // refill just-consumed buffer
        }
    }

    // epilogue: coalesced stores
    float* op = out + ((size_t)o0 * Hh + h) * Ww + w;
    #pragma unroll
    for (int bp = 0; bp < 4; bp++)
        #pragma unroll
        for (int oo = 0; oo < 4; oo++) {
            float lo, hi;
            unpack2(lo, hi, acc2[oo][bp]);
            op[(size_t)((2 * bp)     * Oo + oo) * (Hh * Ww)] = lo;
            op[(size_t)((2 * bp + 1) * Oo + oo) * (Hh * Ww)] = hi;
        }
}

extern "C" void kernel_launch(void* const* d_in, const int* in_sizes, int n_in,
                              void* d_out, int out_size)
{
    const float* x  = (const float*)d_in[0];
    const float* wt = (const float*)d_in[1];
    float* out      = (float*)d_out;

    cudaFuncSetAttribute(lc2d_kernel,
                         cudaFuncAttributeMaxDynamicSharedMemorySize, SMEM_BYTES);

    dim3 grid(Hh, Oo / OTILE);   // 64 x 8 = 512 blocks of 128 threads
    lc2d_kernel<<<grid, 128, SMEM_BYTES>>>(x, wt, out);
}